// round 4
// baseline (speedup 1.0000x reference)
#include <cuda_runtime.h>
#include <cuda_bf16.h>

#define BATCH   16384
#define INF     256
#define GATES   1023
#define GPAD    1024
#define OUTF    128
#define LEAVES  1024

// Scratch: static device globals (no runtime allocation).
__device__ float g_gat[BATCH * GPAD];    // 64 MB: sigmoid gatings, padded stride 1024
__device__ float g_leaf[BATCH * LEAVES]; // 64 MB: leaf densities

// ---------------------------------------------------------------------------
// K1: gatings = sigmoid(x @ gw + gb)
//     M=16384, N=1023(pad 1024), K=256.  CTA tile 128x128, thread tile 8x8.
//     grid (8, 128), block 256.
// ---------------------------------------------------------------------------
__global__ __launch_bounds__(256) void k_gate(const float* __restrict__ x,
                                              const float* __restrict__ gw,
                                              const float* __restrict__ gb) {
    __shared__ __align__(16) float As[16][128];   // [k][m]
    __shared__ __align__(16) float Bs[16][128];   // [k][n]
    const int tid = threadIdx.x;
    const int tr = tid / 16;        // 0..15 -> rows tr*8
    const int tc = tid % 16;        // 0..15 -> cols tc*8
    const int m0 = blockIdx.y * 128;
    const int n0 = blockIdx.x * 128;

    float acc[8][8] = {};

    for (int k0 = 0; k0 < INF; k0 += 16) {
        // A tile: 128 rows x 16 k  (x is [M,256] row-major, 16B-aligned rows)
        #pragma unroll
        for (int i = 0; i < 2; i++) {
            int f4  = tid + i * 256;          // 0..511
            int row = f4 >> 2;
            int kq  = f4 & 3;
            float4 v = *reinterpret_cast<const float4*>(
                &x[(size_t)(m0 + row) * INF + k0 + kq * 4]);
            As[kq * 4 + 0][row] = v.x;
            As[kq * 4 + 1][row] = v.y;
            As[kq * 4 + 2][row] = v.z;
            As[kq * 4 + 3][row] = v.w;
        }
        // B tile: 16 k x 128 n (gw row stride 1023 -> scalar loads, guard n)
        #pragma unroll
        for (int i = 0; i < 8; i++) {
            int e  = tid + i * 256;           // 0..2047
            int kr = e >> 7;
            int nc = e & 127;
            int n  = n0 + nc;
            Bs[kr][nc] = (n < GATES) ? gw[(size_t)(k0 + kr) * GATES + n] : 0.f;
        }
        __syncthreads();

        #pragma unroll
        for (int kk = 0; kk < 16; kk++) {
            float a[8], b[8];
            *(float4*)&a[0] = *(float4*)&As[kk][tr * 8];
            *(float4*)&a[4] = *(float4*)&As[kk][tr * 8 + 4];
            *(float4*)&b[0] = *(float4*)&Bs[kk][tc * 8];
            *(float4*)&b[4] = *(float4*)&Bs[kk][tc * 8 + 4];
            #pragma unroll
            for (int i = 0; i < 8; i++)
                #pragma unroll
                for (int j = 0; j < 8; j++)
                    acc[i][j] = fmaf(a[i], b[j], acc[i][j]);
        }
        __syncthreads();
    }

    // epilogue: + gb, sigmoid, store to padded gatings
    #pragma unroll
    for (int i = 0; i < 8; i++) {
        int m = m0 + tr * 8 + i;
        #pragma unroll
        for (int j = 0; j < 8; j++) {
            int n = n0 + tc * 8 + j;
            if (n < GATES) {
                float v = acc[i][j] + gb[n];
                g_gat[(size_t)m * GPAD + n] = 1.f / (1.f + __expf(-v));
            }
        }
    }
}

// ---------------------------------------------------------------------------
// K2: leaf densities via level-by-level tree expansion.
//     One row per warp (8 rows / CTA), ping-pong smem buffers.
//     child 2i   = dens_i * g_i
//     child 2i+1 = dens_i * (1 - g_i),  g at gating column (2^d - 1 + i).
//     grid BATCH/8 = 2048, block 256.
// ---------------------------------------------------------------------------
__global__ __launch_bounds__(256) void k_leaf() {
    __shared__ __align__(16) float bufA[8][512];
    __shared__ __align__(16) float bufB[8][1024];
    const int w    = threadIdx.x >> 5;
    const int lane = threadIdx.x & 31;
    const int row  = blockIdx.x * 8 + w;
    const float* __restrict__ gr = &g_gat[(size_t)row * GPAD];

    if (lane == 0) bufB[w][0] = 1.f;
    __syncwarp();

    for (int d = 0; d < 10; d++) {
        const int n     = 1 << d;
        const int start = n - 1;
        // writes: even d -> bufA, odd d -> bufB (so d=9 lands in bufB)
        float* src = (d & 1) ? bufA[w] : bufB[w];
        float* dst = (d & 1) ? bufB[w] : bufA[w];
        for (int i = lane; i < n; i += 32) {
            float p = src[i];
            float g = gr[start + i];
            dst[2 * i]     = p * g;
            dst[2 * i + 1] = p * (1.f - g);
        }
        __syncwarp();
    }

    float* __restrict__ out = &g_leaf[(size_t)row * LEAVES];
    #pragma unroll
    for (int j = 0; j < 8; j++) {
        int i = (j * 32 + lane) * 4;
        *reinterpret_cast<float4*>(&out[i]) =
            *reinterpret_cast<float4*>(&bufB[w][i]);
    }
}

// ---------------------------------------------------------------------------
// K3: out = leaf @ z^T.   M=16384, N=128, K=1024.
//     CTA tile 64x128, thread tile 4x8. grid 256, block 256.
//     z is [128,1024] row-major -> B[k][o] = z[o][k].
// ---------------------------------------------------------------------------
__global__ __launch_bounds__(256) void k_out(const float* __restrict__ z,
                                             float* __restrict__ out) {
    __shared__ __align__(16) float As[16][64];    // [k][m]
    __shared__ __align__(16) float Bs[16][128];   // [k][o]
    const int tid = threadIdx.x;
    const int tr  = tid / 16;        // rows tr*4
    const int tc  = tid % 16;        // cols tc*8
    const int m0  = blockIdx.x * 64;

    float acc[4][8] = {};

    for (int k0 = 0; k0 < LEAVES; k0 += 16) {
        // A tile: 64 rows x 16 k  (leaf stride 1024, aligned)
        {
            int f4  = tid;                      // 0..255
            int row = f4 >> 2;
            int kq  = f4 & 3;
            float4 v = *reinterpret_cast<const float4*>(
                &g_leaf[(size_t)(m0 + row) * LEAVES + k0 + kq * 4]);
            As[kq * 4 + 0][row] = v.x;
            As[kq * 4 + 1][row] = v.y;
            As[kq * 4 + 2][row] = v.z;
            As[kq * 4 + 3][row] = v.w;
        }
        // B tile: 128 o x 16 k  (z stride 1024, aligned)
        #pragma unroll
        for (int i = 0; i < 2; i++) {
            int f4 = tid + i * 256;             // 0..511
            int o  = f4 >> 2;
            int kq = f4 & 3;
            float4 v = *reinterpret_cast<const float4*>(
                &z[(size_t)o * LEAVES + k0 + kq * 4]);
            Bs[kq * 4 + 0][o] = v.x;
            Bs[kq * 4 + 1][o] = v.y;
            Bs[kq * 4 + 2][o] = v.z;
            Bs[kq * 4 + 3][o] = v.w;
        }
        __syncthreads();

        #pragma unroll
        for (int kk = 0; kk < 16; kk++) {
            float a[4], b[8];
            *(float4*)&a[0] = *(float4*)&As[kk][tr * 4];
            *(float4*)&b[0] = *(float4*)&Bs[kk][tc * 8];
            *(float4*)&b[4] = *(float4*)&Bs[kk][tc * 8 + 4];
            #pragma unroll
            for (int i = 0; i < 4; i++)
                #pragma unroll
                for (int j = 0; j < 8; j++)
                    acc[i][j] = fmaf(a[i], b[j], acc[i][j]);
        }
        __syncthreads();
    }

    #pragma unroll
    for (int i = 0; i < 4; i++) {
        int m = m0 + tr * 4 + i;
        #pragma unroll
        for (int j = 0; j < 8; j += 4) {
            float4 v = make_float4(acc[i][j], acc[i][j + 1],
                                   acc[i][j + 2], acc[i][j + 3]);
            *reinterpret_cast<float4*>(&out[(size_t)m * OUTF + tc * 8 + j]) = v;
        }
    }
}

// ---------------------------------------------------------------------------
extern "C" void kernel_launch(void* const* d_in, const int* in_sizes, int n_in,
                              void* d_out, int out_size) {
    const float* x  = (const float*)d_in[0];   // [16384, 256]
    const float* gw = (const float*)d_in[1];   // [256, 1023]
    const float* gb = (const float*)d_in[2];   // [1023]
    const float* z  = (const float*)d_in[3];   // [128, 1024]
    float* out = (float*)d_out;                // [16384, 128]

    dim3 g1(GPAD / 128, BATCH / 128);          // (8, 128)
    k_gate<<<g1, 256>>>(x, gw, gb);
    k_leaf<<<BATCH / 8, 256>>>();
    k_out<<<BATCH / 64, 256>>>(z, out);
}

// round 9
// speedup vs baseline: 2.0828x; 2.0828x over previous
#include <cuda_runtime.h>
#include <cuda_bf16.h>
#include <cstdint>

#define BATCH   16384
#define INF     256
#define GATES   1023
#define GPAD    1024
#define OUTF    128
#define LEAVES  1024
#define K1P     768      // 3 * 256  (Ah|Ah|Al) x (Bh|Bl|Bh)
#define K3P     3072     // 3 * 1024

// ---------------- device scratch (static, no runtime allocation) ----------
__device__ __nv_bfloat16 g_xs[BATCH * K1P];            // x'  [16384][768]
__device__ __nv_bfloat16 g_gws[GPAD * K1P];            // gw'^T [1024][768] (row 1023 = 0)
__device__ __nv_bfloat16 g_zs[OUTF * K3P];             // z'  [128][3072]
__device__ __nv_bfloat16 g_ls[(size_t)BATCH * K3P];    // leaf' [16384][3072]
__device__ float         g_gat[BATCH * GPAD];          // sigmoid gatings (fp32)

// ---------------- PTX helpers (all base sm_80-class, compile on compute_103)
__device__ __forceinline__ uint32_t smem_u32(const void* p) {
    uint32_t a;
    asm("{ .reg .u64 t; cvta.to.shared.u64 t, %1; cvt.u32.u64 %0, t; }"
        : "=r"(a) : "l"(p));
    return a;
}
#define CP16(dst, src) \
    asm volatile("cp.async.cg.shared.global [%0], [%1], 16;" \
                 :: "r"(dst), "l"(src) : "memory")
#define CPCOMMIT() asm volatile("cp.async.commit_group;" ::: "memory")
#define CPWAIT(n)  asm volatile("cp.async.wait_group %0;" :: "n"(n) : "memory")

__device__ __forceinline__ void ldm4(uint32_t* r, uint32_t addr) {
    asm volatile("ldmatrix.sync.aligned.m8n8.x4.shared.b16 {%0,%1,%2,%3}, [%4];"
                 : "=r"(r[0]), "=r"(r[1]), "=r"(r[2]), "=r"(r[3]) : "r"(addr));
}
__device__ __forceinline__ void mma16816(float* d, const uint32_t* a, const uint32_t* b) {
    asm volatile("mma.sync.aligned.m16n8k16.row.col.f32.bf16.bf16.f32 "
                 "{%0,%1,%2,%3}, {%4,%5,%6,%7}, {%8,%9}, {%0,%1,%2,%3};"
                 : "+f"(d[0]), "+f"(d[1]), "+f"(d[2]), "+f"(d[3])
                 : "r"(a[0]), "r"(a[1]), "r"(a[2]), "r"(a[3]),
                   "r"(b[0]), "r"(b[1]));
}
__device__ __forceinline__ void split2(float v, __nv_bfloat16& h, __nv_bfloat16& l) {
    h = __float2bfloat16(v);
    l = __float2bfloat16(v - __bfloat162float(h));
}

// ---------------- conversion kernels --------------------------------------
// x [16384,256] -> g_xs rows [Ah(0:256) | Ah(256:512) | Al(512:768)]
__global__ __launch_bounds__(256) void conv_x(const float* __restrict__ x) {
    int i = blockIdx.x * 256 + threadIdx.x;           // float4 index
    int row = i >> 6, col = (i & 63) * 4;
    float4 v = reinterpret_cast<const float4*>(x)[i];
    __nv_bfloat16 h[4], l[4];
    split2(v.x, h[0], l[0]); split2(v.y, h[1], l[1]);
    split2(v.z, h[2], l[2]); split2(v.w, h[3], l[3]);
    __nv_bfloat162 h01{h[0], h[1]}, h23{h[2], h[3]}, l01{l[0], l[1]}, l23{l[2], l[3]};
    __nv_bfloat16* r = &g_xs[(size_t)row * K1P + col];
    *reinterpret_cast<__nv_bfloat162*>(r)           = h01;
    *reinterpret_cast<__nv_bfloat162*>(r + 2)       = h23;
    *reinterpret_cast<__nv_bfloat162*>(r + 256)     = h01;
    *reinterpret_cast<__nv_bfloat162*>(r + 258)     = h23;
    *reinterpret_cast<__nv_bfloat162*>(r + 512)     = l01;
    *reinterpret_cast<__nv_bfloat162*>(r + 514)     = l23;
}
// gw [256,1023] -> gw'^T rows n: [Bh(k) | Bl(k+256) | Bh(k+512)], n=1023 zeros
__global__ __launch_bounds__(256) void conv_gwt(const float* __restrict__ gw) {
    int idx = blockIdx.x * 256 + threadIdx.x;         // k*1024 + n, coalesced read
    int k = idx >> 10, n = idx & 1023;
    float v = (n < GATES) ? gw[(size_t)k * GATES + n] : 0.f;
    __nv_bfloat16 h, l;
    split2(v, h, l);
    __nv_bfloat16* r = &g_gws[(size_t)n * K1P];
    r[k] = h; r[256 + k] = l; r[512 + k] = h;
}
// z [128,1024] -> g_zs rows [Bh | Bl | Bh]
__global__ __launch_bounds__(256) void conv_z(const float* __restrict__ z) {
    int i = blockIdx.x * 256 + threadIdx.x;           // float4 index
    int n = i >> 8, col = (i & 255) * 4;
    float4 v = reinterpret_cast<const float4*>(z)[i];
    __nv_bfloat16 h[4], l[4];
    split2(v.x, h[0], l[0]); split2(v.y, h[1], l[1]);
    split2(v.z, h[2], l[2]); split2(v.w, h[3], l[3]);
    __nv_bfloat162 h01{h[0], h[1]}, h23{h[2], h[3]}, l01{l[0], l[1]}, l23{l[2], l[3]};
    __nv_bfloat16* r = &g_zs[(size_t)n * K3P + col];
    *reinterpret_cast<__nv_bfloat162*>(r)            = h01;
    *reinterpret_cast<__nv_bfloat162*>(r + 2)        = h23;
    *reinterpret_cast<__nv_bfloat162*>(r + 1024)     = l01;
    *reinterpret_cast<__nv_bfloat162*>(r + 1026)     = l23;
    *reinterpret_cast<__nv_bfloat162*>(r + 2048)     = h01;
    *reinterpret_cast<__nv_bfloat162*>(r + 2050)     = h23;
}

// ---------------- bf16 HMMA GEMM: D = A' @ B'^T -----------------------------
// CTA 128x128, 8 warps (2x4), warp tile 64x32, K-chunk 32, cp.async 2-stage.
// smem row stride 56 elems (112B: 16B-aligned, conflict-free ldmatrix).
template <int KP, bool SIG>
__global__ __launch_bounds__(256, 2) void k_mma(const float* __restrict__ gb,
                                                float* __restrict__ outp) {
    extern __shared__ __align__(16) char smem[];
    constexpr int NCH = KP / 32;
    constexpr int SST = 56;
    constexpr int ABYTES = 128 * SST * 2;             // 14336
    constexpr int STG = 2 * ABYTES;                   // 28672 per stage

    const __nv_bfloat16* __restrict__ A = SIG ? g_xs  : g_ls;
    const __nv_bfloat16* __restrict__ B = SIG ? g_gws : g_zs;

    const int tid = threadIdx.x, wid = tid >> 5, lane = tid & 31;
    const int m0 = blockIdx.y * 128, n0 = blockIdx.x * 128;
    const int wm = (wid & 1) * 64, wn = (wid >> 1) * 32;
    const uint32_t sb = smem_u32(smem);

    const __nv_bfloat16* gA = A + (size_t)m0 * KP;
    const __nv_bfloat16* gB = B + (size_t)n0 * KP;

    float acc[4][4][4];
    #pragma unroll
    for (int i = 0; i < 4; i++)
        #pragma unroll
        for (int j = 0; j < 4; j++)
            #pragma unroll
            for (int k = 0; k < 4; k++) acc[i][j][k] = 0.f;

    // ldmatrix lane addressing
    const int arow  = wm + (lane & 15);
    const int ahalf = (lane >> 4) * 8;
    const int brow  = wn + (lane & 7) + ((lane >> 4) << 3);
    const int bkof  = ((lane >> 3) & 1) * 8;

    // G2S: each thread 2x(16B A + 16B B) per chunk
    const int lrow = tid >> 2, lcc = tid & 3;

    auto load_chunk = [&](int c, int s) {
        uint32_t base = sb + s * STG;
        #pragma unroll
        for (int i = 0; i < 2; i++) {
            int row = lrow + i * 64;
            uint32_t so = (uint32_t)(row * SST + lcc * 8) * 2;
            CP16(base + so,          gA + (size_t)row * KP + c * 32 + lcc * 8);
            CP16(base + ABYTES + so, gB + (size_t)row * KP + c * 32 + lcc * 8);
        }
        CPCOMMIT();
    };

    load_chunk(0, 0);
    for (int c = 0; c < NCH; c++) {
        const int s = c & 1;
        if (c + 1 < NCH) { load_chunk(c + 1, s ^ 1); CPWAIT(1); }
        else             { CPWAIT(0); }
        __syncthreads();

        const uint32_t aB = sb + s * STG;
        const uint32_t bB = aB + ABYTES;
        #pragma unroll
        for (int kk = 0; kk < 2; kk++) {
            uint32_t a[4][4], b[2][4];
            #pragma unroll
            for (int mt = 0; mt < 4; mt++)
                ldm4(a[mt], aB + (uint32_t)((arow + mt * 16) * SST + kk * 16 + ahalf) * 2);
            #pragma unroll
            for (int np = 0; np < 2; np++)
                ldm4(b[np], bB + (uint32_t)((brow + np * 16) * SST + kk * 16 + bkof) * 2);
            #pragma unroll
            for (int mt = 0; mt < 4; mt++)
                #pragma unroll
                for (int nt = 0; nt < 4; nt++)
                    mma16816(acc[mt][nt], a[mt], &b[nt >> 1][(nt & 1) * 2]);
        }
        __syncthreads();
    }

    // epilogue: c0,c1 -> (row g, cols 2tg,2tg+1); c2,c3 -> row g+8
    const int mg = m0 + wm + (lane >> 2);
    const int cg = (lane & 3) * 2;
    #pragma unroll
    for (int mt = 0; mt < 4; mt++) {
        const int m = mg + mt * 16;
        #pragma unroll
        for (int nt = 0; nt < 4; nt++) {
            const int n = n0 + wn + nt * 8 + cg;
            float* ac = acc[mt][nt];
            if (SIG) {
                float b0 = (n     < GATES) ? gb[n]     : 0.f;
                float b1 = (n + 1 < GATES) ? gb[n + 1] : 0.f;
                float2 v0{1.f / (1.f + __expf(-(ac[0] + b0))),
                          1.f / (1.f + __expf(-(ac[1] + b1)))};
                float2 v1{1.f / (1.f + __expf(-(ac[2] + b0))),
                          1.f / (1.f + __expf(-(ac[3] + b1)))};
                *reinterpret_cast<float2*>(&g_gat[(size_t)m * GPAD + n])       = v0;
                *reinterpret_cast<float2*>(&g_gat[(size_t)(m + 8) * GPAD + n]) = v1;
            } else {
                *reinterpret_cast<float2*>(&outp[(size_t)m * OUTF + n])       = float2{ac[0], ac[1]};
                *reinterpret_cast<float2*>(&outp[(size_t)(m + 8) * OUTF + n]) = float2{ac[2], ac[3]};
            }
        }
    }
}

// ---------------- K2: leaf densities + split into concat layout -------------
__global__ __launch_bounds__(256) void k_leaf() {
    __shared__ __align__(16) float bufA[8][512];
    __shared__ __align__(16) float bufB[8][1024];
    const int w    = threadIdx.x >> 5;
    const int lane = threadIdx.x & 31;
    const int row  = blockIdx.x * 8 + w;
    const float* __restrict__ gr = &g_gat[(size_t)row * GPAD];

    if (lane == 0) bufB[w][0] = 1.f;
    __syncwarp();

    for (int d = 0; d < 10; d++) {
        const int n = 1 << d, start = n - 1;
        float* src = (d & 1) ? bufA[w] : bufB[w];
        float* dst = (d & 1) ? bufB[w] : bufA[w];
        for (int i = lane; i < n; i += 32) {
            float p = src[i], g = gr[start + i];
            dst[2 * i]     = p * g;
            dst[2 * i + 1] = p * (1.f - g);
        }
        __syncwarp();
    }

    const size_t base = (size_t)row * K3P;
    #pragma unroll
    for (int j = 0; j < 8; j++) {
        int i = (j * 32 + lane) * 4;
        float4 v = *reinterpret_cast<float4*>(&bufB[w][i]);
        __nv_bfloat16 h[4], l[4];
        split2(v.x, h[0], l[0]); split2(v.y, h[1], l[1]);
        split2(v.z, h[2], l[2]); split2(v.w, h[3], l[3]);
        __nv_bfloat162 h01{h[0], h[1]}, h23{h[2], h[3]}, l01{l[0], l[1]}, l23{l[2], l[3]};
        __nv_bfloat16* r = &g_ls[base + i];
        *reinterpret_cast<__nv_bfloat162*>(r)            = h01;   // Ah
        *reinterpret_cast<__nv_bfloat162*>(r + 2)        = h23;
        *reinterpret_cast<__nv_bfloat162*>(r + 1024)     = h01;   // Ah (dup)
        *reinterpret_cast<__nv_bfloat162*>(r + 1026)     = h23;
        *reinterpret_cast<__nv_bfloat162*>(r + 2048)     = l01;   // Al
        *reinterpret_cast<__nv_bfloat162*>(r + 2050)     = l23;
    }
}

// ---------------------------------------------------------------------------
extern "C" void kernel_launch(void* const* d_in, const int* in_sizes, int n_in,
                              void* d_out, int out_size) {
    const float* x  = (const float*)d_in[0];   // [16384, 256]
    const float* gw = (const float*)d_in[1];   // [256, 1023]
    const float* gb = (const float*)d_in[2];   // [1023]
    const float* z  = (const float*)d_in[3];   // [128, 1024]
    float* out = (float*)d_out;                // [16384, 128]

    const int SMEM_SZ = 2 * 28672;             // 57344 B (2 stages)
    static int configured = 0;
    cudaFuncSetAttribute(k_mma<K1P, true>,  cudaFuncAttributeMaxDynamicSharedMemorySize, SMEM_SZ);
    cudaFuncSetAttribute(k_mma<K3P, false>, cudaFuncAttributeMaxDynamicSharedMemorySize, SMEM_SZ);
    (void)configured;

    conv_x  <<<(BATCH * INF / 4) / 256, 256>>>(x);
    conv_gwt<<<(INF * GPAD) / 256, 256>>>(gw);
    conv_z  <<<(OUTF * LEAVES / 4) / 256, 256>>>(z);

    k_mma<K1P, true><<<dim3(GPAD / 128, BATCH / 128), 256, SMEM_SZ>>>(gb, out);  // -> g_gat
    k_leaf<<<BATCH / 8, 256>>>();                                                // -> g_ls
    k_mma<K3P, false><<<dim3(1, BATCH / 128), 256, SMEM_SZ>>>(gb, out);          // -> out
}